// round 4
// baseline (speedup 1.0000x reference)
#include <cuda_runtime.h>

// Ragged segment mean: out[b,d] = mean(seq[b, begin[b]:end[b], d])
// B=2048, L=512, D=512, fp32.
//
// Load balancing: one CTA per batch was a single full wave (2048 CTAs = one
// residency set), so per-SM work variance (sum of ~14 uniform segment
// lengths) created a straggler tail with DRAM idle. Now J=4 CTAs per batch
// process interleaved rows -> 8192 CTAs, 3.5 waves, <=64 rows per CTA; the
// scheduler rebalances across waves. Partials go to a __device__ scratch;
// a small combine kernel sums and divides.

static constexpr int L_DIM = 512;
static constexpr int D_DIM = 512;
static constexpr int D_VEC = D_DIM / 4;   // 128 float4 per row
static constexpr int B_DIM = 2048;
static constexpr int J     = 4;           // split factor per batch

// 4 * 2048 * 512 floats = 16 MB scratch
__device__ float g_partial[(size_t)J * B_DIM * D_DIM];

__global__ __launch_bounds__(128) void ragged_partial_kernel(
    const float* __restrict__ seq,
    const int*   __restrict__ begin,
    const int*   __restrict__ end)
{
    const int b = blockIdx.x;
    const int j = blockIdx.y;             // 0..J-1
    const int t = threadIdx.x;            // 0..127

    const int s = begin[b];
    const int e = end[b];

    const float4* __restrict__ base =
        reinterpret_cast<const float4*>(seq) + (size_t)b * L_DIM * D_VEC + t;

    float ax = 0.f, ay = 0.f, az = 0.f, aw = 0.f;

    int l = s + j;
    // rows for this CTA: l, l+J, l+2J, ... ; unroll 4 for MLP
    for (; l + 3 * J < e; l += 4 * J) {
        float4 v0 = base[(size_t)(l + 0 * J) * D_VEC];
        float4 v1 = base[(size_t)(l + 1 * J) * D_VEC];
        float4 v2 = base[(size_t)(l + 2 * J) * D_VEC];
        float4 v3 = base[(size_t)(l + 3 * J) * D_VEC];
        ax += v0.x; ay += v0.y; az += v0.z; aw += v0.w;
        ax += v1.x; ay += v1.y; az += v1.z; aw += v1.w;
        ax += v2.x; ay += v2.y; az += v2.z; aw += v2.w;
        ax += v3.x; ay += v3.y; az += v3.z; aw += v3.w;
    }
    // 2-row step before scalar tail (keeps 2 loads in flight)
    for (; l + J < e; l += 2 * J) {
        float4 v0 = base[(size_t)l * D_VEC];
        float4 v1 = base[(size_t)(l + J) * D_VEC];
        ax += v0.x; ay += v0.y; az += v0.z; aw += v0.w;
        ax += v1.x; ay += v1.y; az += v1.z; aw += v1.w;
    }
    if (l < e) {
        float4 v = base[(size_t)l * D_VEC];
        ax += v.x; ay += v.y; az += v.z; aw += v.w;
    }

    float4 r; r.x = ax; r.y = ay; r.z = az; r.w = aw;
    reinterpret_cast<float4*>(g_partial)[((size_t)j * B_DIM + b) * D_VEC + t] = r;
}

__global__ __launch_bounds__(128) void ragged_combine_kernel(
    const int* __restrict__ begin,
    const int* __restrict__ end,
    float*     __restrict__ out)
{
    const int b = blockIdx.x;
    const int t = threadIdx.x;

    const float4* __restrict__ p = reinterpret_cast<const float4*>(g_partial);

    float4 p0 = p[((size_t)0 * B_DIM + b) * D_VEC + t];
    float4 p1 = p[((size_t)1 * B_DIM + b) * D_VEC + t];
    float4 p2 = p[((size_t)2 * B_DIM + b) * D_VEC + t];
    float4 p3 = p[((size_t)3 * B_DIM + b) * D_VEC + t];

    const float inv = 1.0f / (float)(end[b] - begin[b]);

    float4 r;
    r.x = (p0.x + p1.x + p2.x + p3.x) * inv;
    r.y = (p0.y + p1.y + p2.y + p3.y) * inv;
    r.z = (p0.z + p1.z + p2.z + p3.z) * inv;
    r.w = (p0.w + p1.w + p2.w + p3.w) * inv;

    reinterpret_cast<float4*>(out)[(size_t)b * D_VEC + t] = r;
}

extern "C" void kernel_launch(void* const* d_in, const int* in_sizes, int n_in,
                              void* d_out, int out_size)
{
    const float* seq   = (const float*)d_in[0];
    const int*   begin = (const int*)d_in[1];
    const int*   end   = (const int*)d_in[2];
    float*       out   = (float*)d_out;

    const int B = in_sizes[1];   // 2048

    dim3 grid1(B, J);
    ragged_partial_kernel<<<grid1, 128>>>(seq, begin, end);
    ragged_combine_kernel<<<B, 128>>>(begin, end, out);
}